// round 7
// baseline (speedup 1.0000x reference)
#include <cuda_runtime.h>
#include <cstdint>
#include <cstddef>

// ---------------- problem constants ----------------
#define DIMD   2048
#define MTOT   16384            // 4*4096 tokens
#define N1     6144             // 3*DIMD
#define KD     2048
#define SEQ    4096

// ---------------- scratch (k-permuted layouts for GEMM operands) ----------
// Within each 8-element k-group, position j holds k = (j&1)*4 + (j>>1):
// order [0,4,1,5,2,6,3,7]. So (k=t, k=t+4) sit adjacent -> LDS.64 frag loads.
__device__ float g_xn[(size_t)MTOT * KD];
__device__ float g_h [(size_t)MTOT * N1];
__device__ float g_o [(size_t)MTOT * KD];
__device__ float g_We[(size_t)N1  * KD];
__device__ float g_Wp[(size_t)KD  * KD];

// ---------------- helpers ----------------
__device__ __forceinline__ float to_tf32(float x) {
    float r; asm("cvt.rna.tf32.f32 %0, %1;" : "=f"(r) : "f"(x)); return r;
}
__device__ __forceinline__ void cpasync16(void* smem, const void* gmem) {
    uint32_t s = (uint32_t)__cvta_generic_to_shared(smem);
    asm volatile("cp.async.cg.shared.global [%0], [%1], 16;" :: "r"(s), "l"(gmem));
}
#define CP_COMMIT() asm volatile("cp.async.commit_group;")
#define CP_WAIT1()  asm volatile("cp.async.wait_group 1;")

__device__ __forceinline__ void mma_tf32(float c[4], const uint32_t a[4], const uint32_t b[2]) {
    asm volatile(
        "mma.sync.aligned.m16n8k8.row.col.f32.tf32.tf32.f32 "
        "{%0,%1,%2,%3}, {%4,%5,%6,%7}, {%8,%9}, {%0,%1,%2,%3};"
        : "+f"(c[0]), "+f"(c[1]), "+f"(c[2]), "+f"(c[3])
        : "r"(a[0]), "r"(a[1]), "r"(a[2]), "r"(a[3]),
          "r"(b[0]), "r"(b[1]));
}

// interleave 8 consecutive-k floats into permuted order [0,4,1,5,2,6,3,7]
__device__ __forceinline__ void perm_store8(float* dst, float4 a, float4 b) {
    float4 o0, o1;
    o0.x = a.x; o0.y = b.x; o0.z = a.y; o0.w = b.y;
    o1.x = a.z; o1.y = b.z; o1.z = a.w; o1.w = b.w;
    ((float4*)dst)[0] = o0;
    ((float4*)dst)[1] = o1;
}

// ---------------- tf32 GEMM v7: C[M,N] = A[M,K] * B[N,K]^T ----------------
// R4 config (best): CTA 128x256, 8 warps (2Mx4N), warp tile 64x64, BK=32,
// NSTG=3, register ping-pong fragments. New: k-permuted operands -> fragment
// loads are LDS.64 (16 per ks instead of 32 LDS.32).
constexpr int BM = 128, BN = 256, BK = 32, NSTG = 3;
constexpr int LDS_STRIDE = BK + 4;                   // 36 floats
constexpr int A_FLOATS = BM * LDS_STRIDE;            // 4608
constexpr int B_FLOATS = BN * LDS_STRIDE;            // 9216
constexpr int STG_FLOATS = A_FLOATS + B_FLOATS;      // 13824
constexpr int SMEM_SZ = NSTG * STG_FLOATS * 4;       // 165888 B

template<int N, bool FUSE>
__global__ void __launch_bounds__(256, 1) gemm_k(const float* __restrict__ A,
                                                 const float* __restrict__ B,
                                                 float* __restrict__ C,
                                                 const float* __restrict__ xres,
                                                 const float* __restrict__ cs) {
    constexpr int K = KD;
    constexpr int KT = K / BK;    // 64
    extern __shared__ float smem[];

    const int bm = blockIdx.y * BM;
    const int bn = blockIdx.x * BN;
    const int tid  = threadIdx.x;
    const int warp = tid >> 5, lane = tid & 31;
    const int wm = (warp & 1) * 64;
    const int wn = (warp >> 1) * 64;
    const int gid = lane >> 2, tig = lane & 3;

    float acc[4][8][4];
    #pragma unroll
    for (int mi = 0; mi < 4; mi++)
        #pragma unroll
        for (int ni = 0; ni < 8; ni++)
            #pragma unroll
            for (int r = 0; r < 4; r++) acc[mi][ni][r] = 0.f;

    const float* Abase = A + (size_t)bm * K;
    const float* Bbase = B + (size_t)bn * K;

    auto load_stage = [&](int kt) {
        float* sa = smem + (kt % NSTG) * STG_FLOATS;
        float* sb = sa + A_FLOATS;
        const float* Ag = Abase + kt * BK;
        const float* Bg = Bbase + kt * BK;
        // A: 128 rows x 8 chunks(16B) = 1024, 4 per thread
        #pragma unroll
        for (int i = 0; i < 4; i++) {
            int c = tid + i * 256;
            int row = c >> 3, ck = c & 7;
            cpasync16(sa + row * LDS_STRIDE + ck * 4, Ag + (size_t)row * K + ck * 4);
        }
        // B: 256 rows x 8 chunks = 2048, 8 per thread
        #pragma unroll
        for (int i = 0; i < 8; i++) {
            int c = tid + i * 256;
            int row = c >> 3, ck = c & 7;
            cpasync16(sb + row * LDS_STRIDE + ck * 4, Bg + (size_t)row * K + ck * 4);
        }
    };

    uint32_t fa[2][4][4];
    uint32_t fb[2][8][2];

    // permuted layout: float2 at (row, ks*8 + 2*tig) = {k=tig, k=tig+4}
    auto load_frags = [&](int buf, int stage, int ks) {
        const float* sa = smem + stage * STG_FLOATS;
        const float* sb = sa + A_FLOATS;
        const int f2off = ks * 4 + tig;       // in float2 units
        #pragma unroll
        for (int mi = 0; mi < 4; mi++) {
            const int r = wm + mi * 16 + gid;
            float2 v = ((const float2*)(sa + r * LDS_STRIDE))[f2off];
            float2 w = ((const float2*)(sa + (r + 8) * LDS_STRIDE))[f2off];
            fa[buf][mi][0] = __float_as_uint(v.x);
            fa[buf][mi][1] = __float_as_uint(w.x);
            fa[buf][mi][2] = __float_as_uint(v.y);
            fa[buf][mi][3] = __float_as_uint(w.y);
        }
        #pragma unroll
        for (int ni = 0; ni < 8; ni++) {
            const int r = wn + ni * 8 + gid;
            float2 u = ((const float2*)(sb + r * LDS_STRIDE))[f2off];
            fb[buf][ni][0] = __float_as_uint(u.x);
            fb[buf][ni][1] = __float_as_uint(u.y);
        }
    };

    auto mma_all = [&](int buf) {
        #pragma unroll
        for (int mi = 0; mi < 4; mi++)
            #pragma unroll
            for (int ni = 0; ni < 8; ni++)
                mma_tf32(acc[mi][ni], fa[buf][mi], fb[buf][ni]);
    };

    // prologue: 2 stages in flight
    load_stage(0); CP_COMMIT();
    load_stage(1); CP_COMMIT();
    CP_WAIT1();
    __syncthreads();
    load_frags(0, 0, 0);

    #pragma unroll 1
    for (int kt = 0; kt < KT; kt++) {
        const int stage = kt % NSTG;

        // ks0 (buf0 preloaded)
        load_frags(1, stage, 1);
        if (kt + 2 < KT) load_stage(kt + 2);
        CP_COMMIT();
        mma_all(0);
        // ks1
        load_frags(0, stage, 2);
        mma_all(1);
        // ks2
        load_frags(1, stage, 3);
        mma_all(0);
        // ks3
        if (kt + 1 < KT) {
            CP_WAIT1();
            __syncthreads();
            load_frags(0, (kt + 1) % NSTG, 0);
        }
        mma_all(1);
    }

    // epilogue
    #pragma unroll
    for (int mi = 0; mi < 4; mi++) {
        #pragma unroll
        for (int ni = 0; ni < 8; ni++) {
            int r0 = bm + wm + mi * 16 + gid;
            int c0 = bn + wn + ni * 8 + tig * 2;
            #pragma unroll
            for (int h = 0; h < 2; h++) {
                int r = r0 + h * 8;
                size_t off = (size_t)r * N + c0;
                float v0 = acc[mi][ni][2 * h + 0];
                float v1 = acc[mi][ni][2 * h + 1];
                if (FUSE) {
                    v0 = xres[off]     + cs[c0]     * v0;
                    v1 = xres[off + 1] + cs[c0 + 1] * v1;
                }
                float2 st; st.x = v0; st.y = v1;
                *(float2*)(C + off) = st;
            }
        }
    }
}

// ---------------- prep: round weights to tf32 + k-permute ----------------
template<size_t TOTAL>
__global__ void round_perm_k(const float* __restrict__ src, float* __restrict__ dst) {
    size_t i = (size_t)blockIdx.x * blockDim.x + threadIdx.x;   // 8-group index
    if (i >= TOTAL / 8) return;
    float4 a = ((const float4*)src)[2 * i];
    float4 b = ((const float4*)src)[2 * i + 1];
    a.x = to_tf32(a.x); a.y = to_tf32(a.y); a.z = to_tf32(a.z); a.w = to_tf32(a.w);
    b.x = to_tf32(b.x); b.y = to_tf32(b.y); b.z = to_tf32(b.z); b.w = to_tf32(b.w);
    perm_store8(dst + 8 * i, a, b);
}

// ---------------- rmsnorm (emits k-permuted tf32 rows) ----------------
__global__ void __launch_bounds__(256) rmsnorm_k(const float* __restrict__ x) {
    int row = blockIdx.x;
    const float4* xr = (const float4*)(x + (size_t)row * DIMD);
    float* outr = g_xn + (size_t)row * DIMD;
    int t = threadIdx.x;               // thread t owns 8-group t (8 floats)

    float4 a = xr[2 * t];
    float4 b = xr[2 * t + 1];
    float ss = a.x*a.x + a.y*a.y + a.z*a.z + a.w*a.w
             + b.x*b.x + b.y*b.y + b.z*b.z + b.w*b.w;
    #pragma unroll
    for (int off = 16; off > 0; off >>= 1)
        ss += __shfl_xor_sync(0xffffffffu, ss, off);

    __shared__ float red[8];
    __shared__ float sscale;
    int warp = t >> 5, lane = t & 31;
    if (lane == 0) red[warp] = ss;
    __syncthreads();
    if (t == 0) {
        float tot = 0.f;
        #pragma unroll
        for (int i = 0; i < 8; i++) tot += red[i];
        sscale = rsqrtf(tot * (1.0f / DIMD) + 1.1920928955078125e-07f);
    }
    __syncthreads();
    float sc = sscale;
    a.x = to_tf32(a.x * sc); a.y = to_tf32(a.y * sc); a.z = to_tf32(a.z * sc); a.w = to_tf32(a.w * sc);
    b.x = to_tf32(b.x * sc); b.y = to_tf32(b.y * sc); b.z = to_tf32(b.z * sc); b.w = to_tf32(b.w * sc);
    perm_store8(outr + 8 * t, a, b);
}

// ---------------- gate * causal dwconv * gate (emits k-permuted o) -------
// Each thread handles channel pair (d, d+4) of one token -> float2 store at
// permuted position. d = gi*8 + j, partner d+4, stored at pos gi*8 + 2*j.
__global__ void __launch_bounds__(256) gateconv_k(const float* __restrict__ cw,
                                                  const float* __restrict__ cb,
                                                  const int* __restrict__ dil_p) {
    int dil = *dil_p;
    size_t idx = (size_t)blockIdx.x * blockDim.x + threadIdx.x;
    if (idx >= (size_t)MTOT * (DIMD / 2)) return;
    int r = (int)(idx % (DIMD / 2));
    int m = (int)(idx / (DIMD / 2));
    int s = m % SEQ;
    int gi = r >> 2, j = r & 3;
    int d0 = gi * 8 + j;
    int d1 = d0 + 4;

    const float* hr = g_h + (size_t)m * N1;
    float w00 = cw[d0 * 3 + 0], w01 = cw[d0 * 3 + 1], w02 = cw[d0 * 3 + 2];
    float w10 = cw[d1 * 3 + 0], w11 = cw[d1 * 3 + 1], w12 = cw[d1 * 3 + 2];

    float a0 = cb[d0] + w02 * (hr[d0] * hr[2 * DIMD + d0]);
    float a1 = cb[d1] + w12 * (hr[d1] * hr[2 * DIMD + d1]);
    if (s >= dil) {
        const float* hp = hr - (size_t)dil * N1;
        a0 += w01 * (hp[d0] * hp[2 * DIMD + d0]);
        a1 += w11 * (hp[d1] * hp[2 * DIMD + d1]);
    }
    if (s >= 2 * dil) {
        const float* hp = hr - (size_t)(2 * dil) * N1;
        a0 += w00 * (hp[d0] * hp[2 * DIMD + d0]);
        a1 += w10 * (hp[d1] * hp[2 * DIMD + d1]);
    }
    float2 o;
    o.x = to_tf32(hr[DIMD + d0] * a0);
    o.y = to_tf32(hr[DIMD + d1] * a1);
    *(float2*)(g_o + (size_t)m * DIMD + gi * 8 + 2 * j) = o;
}

// ---------------- launch ----------------
extern "C" void kernel_launch(void* const* d_in, const int* in_sizes, int n_in,
                              void* d_out, int out_size) {
    const float* x   = (const float*)d_in[0];
    const float* We  = (const float*)d_in[1];
    const float* cw  = (const float*)d_in[2];
    const float* cb  = (const float*)d_in[3];
    const float* Wp  = (const float*)d_in[4];
    const float* cs  = (const float*)d_in[5];
    const int*   dil = (const int*)  d_in[6];
    float* out = (float*)d_out;

    float *p_xn, *p_h, *p_o, *p_We, *p_Wp;
    cudaGetSymbolAddress((void**)&p_xn, g_xn);
    cudaGetSymbolAddress((void**)&p_h,  g_h);
    cudaGetSymbolAddress((void**)&p_o,  g_o);
    cudaGetSymbolAddress((void**)&p_We, g_We);
    cudaGetSymbolAddress((void**)&p_Wp, g_Wp);

    cudaFuncSetAttribute(gemm_k<N1, false>, cudaFuncAttributeMaxDynamicSharedMemorySize, SMEM_SZ);
    cudaFuncSetAttribute(gemm_k<KD, true >, cudaFuncAttributeMaxDynamicSharedMemorySize, SMEM_SZ);

    {
        constexpr size_t TWE = (size_t)N1 * KD;
        constexpr size_t TWP = (size_t)KD * KD;
        round_perm_k<TWE><<<(unsigned)((TWE / 8 + 255) / 256), 256>>>(We, p_We);
        round_perm_k<TWP><<<(unsigned)((TWP / 8 + 255) / 256), 256>>>(Wp, p_Wp);
    }

    rmsnorm_k<<<MTOT, 256>>>(x);

    // h = xn @ We^T   [16384 x 6144]
    gemm_k<N1, false><<<dim3(N1 / BN, MTOT / BM), 256, SMEM_SZ>>>(p_xn, p_We, p_h, nullptr, nullptr);

    {
        size_t n = (size_t)MTOT * (DIMD / 2);
        gateconv_k<<<(unsigned)((n + 255) / 256), 256>>>(cw, cb, dil);
    }

    // out = x + cs * (o @ Wp^T)   [16384 x 2048]
    gemm_k<KD, true><<<dim3(KD / BN, MTOT / BM), 256, SMEM_SZ>>>(p_o, p_Wp, out, x, cs);
}

// round 8
// speedup vs baseline: 1.2284x; 1.2284x over previous
#include <cuda_runtime.h>
#include <cstdint>
#include <cstddef>

// ---------------- problem constants ----------------
#define DIMD   2048
#define MTOT   16384            // 4*4096 tokens
#define N1     6144             // 3*DIMD
#define KD     2048
#define SEQ    4096

// ---------------- scratch ----------------
__device__ float g_xn[(size_t)MTOT * KD];
__device__ float g_h [(size_t)MTOT * N1];
__device__ float g_o [(size_t)MTOT * KD];
__device__ float g_We[(size_t)N1  * KD];
__device__ float g_Wp[(size_t)KD  * KD];

// ---------------- helpers ----------------
__device__ __forceinline__ float to_tf32(float x) {
    float r; asm("cvt.rna.tf32.f32 %0, %1;" : "=f"(r) : "f"(x)); return r;
}
__device__ __forceinline__ void cpasync16(void* smem, const void* gmem) {
    uint32_t s = (uint32_t)__cvta_generic_to_shared(smem);
    asm volatile("cp.async.cg.shared.global [%0], [%1], 16;" :: "r"(s), "l"(gmem));
}
#define CP_COMMIT() asm volatile("cp.async.commit_group;")
#define CP_WAIT1()  asm volatile("cp.async.wait_group 1;")

__device__ __forceinline__ uint32_t lds32(uint32_t a) {
    uint32_t v;
    asm volatile("ld.shared.b32 %0, [%1];" : "=r"(v) : "r"(a));
    return v;
}

__device__ __forceinline__ void mma_tf32(float c[4], const uint32_t a[4], const uint32_t b[2]) {
    asm volatile(
        "mma.sync.aligned.m16n8k8.row.col.f32.tf32.tf32.f32 "
        "{%0,%1,%2,%3}, {%4,%5,%6,%7}, {%8,%9}, {%0,%1,%2,%3};"
        : "+f"(c[0]), "+f"(c[1]), "+f"(c[2]), "+f"(c[3])
        : "r"(a[0]), "r"(a[1]), "r"(a[2]), "r"(a[3]),
          "r"(b[0]), "r"(b[1]));
}

// ---------------- tf32 GEMM v8: C[M,N] = A[M,K] * B[N,K]^T ----------------
// R4 config: CTA 128x256, 8 warps (2Mx4N), warp tile 64x64, BK=32, NSTG=3,
// register ping-pong fragments. New: fragment loads are volatile ld.shared
// INTERLEAVED with MMA groups (8 loads : 8 MMAs) so the tensor pipe starts
// immediately each ks instead of waiting behind a 32-load batch.
constexpr int BM = 128, BN = 256, BK = 32, NSTG = 3;
constexpr int LDS_STRIDE = BK + 4;                   // 36 floats
constexpr int A_FLOATS = BM * LDS_STRIDE;            // 4608
constexpr int B_FLOATS = BN * LDS_STRIDE;            // 9216
constexpr int STG_FLOATS = A_FLOATS + B_FLOATS;      // 13824
constexpr int STG_BYTES  = STG_FLOATS * 4;
constexpr int SMEM_SZ = NSTG * STG_BYTES;            // 165888 B

template<int N, bool FUSE>
__global__ void __launch_bounds__(256, 1) gemm_k(const float* __restrict__ A,
                                                 const float* __restrict__ B,
                                                 float* __restrict__ C,
                                                 const float* __restrict__ xres,
                                                 const float* __restrict__ cs) {
    constexpr int K = KD;
    constexpr int KT = K / BK;    // 64
    extern __shared__ float smem[];
    const uint32_t sbase = (uint32_t)__cvta_generic_to_shared(smem);

    const int bm = blockIdx.y * BM;
    const int bn = blockIdx.x * BN;
    const int tid  = threadIdx.x;
    const int warp = tid >> 5, lane = tid & 31;
    const int wm = (warp & 1) * 64;
    const int wn = (warp >> 1) * 64;
    const int gid = lane >> 2, tig = lane & 3;

    float acc[4][8][4];
    #pragma unroll
    for (int mi = 0; mi < 4; mi++)
        #pragma unroll
        for (int ni = 0; ni < 8; ni++)
            #pragma unroll
            for (int r = 0; r < 4; r++) acc[mi][ni][r] = 0.f;

    const float* Abase = A + (size_t)bm * K;
    const float* Bbase = B + (size_t)bn * K;

    auto load_stage = [&](int kt) {
        float* sa = smem + (kt % NSTG) * STG_FLOATS;
        float* sb = sa + A_FLOATS;
        const float* Ag = Abase + kt * BK;
        const float* Bg = Bbase + kt * BK;
        #pragma unroll
        for (int i = 0; i < 4; i++) {
            int c = tid + i * 256;
            int row = c >> 3, ck = c & 7;
            cpasync16(sa + row * LDS_STRIDE + ck * 4, Ag + (size_t)row * K + ck * 4);
        }
        #pragma unroll
        for (int i = 0; i < 8; i++) {
            int c = tid + i * 256;
            int row = c >> 3, ck = c & 7;
            cpasync16(sb + row * LDS_STRIDE + ck * 4, Bg + (size_t)row * K + ck * 4);
        }
    };

    uint32_t fa[2][4][4];
    uint32_t fb[2][8][2];

    // per-warp invariant smem offsets (bytes)
    const uint32_t aoff = (uint32_t)((wm + gid) * LDS_STRIDE + tig) * 4;
    const uint32_t boff = (uint32_t)((wn + gid) * LDS_STRIDE + tig) * 4;

    // plain (prologue) fragment load for one buffer
    auto load_frags = [&](int buf, uint32_t stg, int ks) {
        const uint32_t sa = stg + aoff + (uint32_t)(ks * 8) * 4;
        const uint32_t sb = stg + (uint32_t)A_FLOATS * 4 + boff + (uint32_t)(ks * 8) * 4;
        #pragma unroll
        for (int mi = 0; mi < 4; mi++) {
            uint32_t p = sa + (uint32_t)(mi * 16 * LDS_STRIDE) * 4;
            fa[buf][mi][0] = lds32(p);
            fa[buf][mi][1] = lds32(p + 8 * LDS_STRIDE * 4);
            fa[buf][mi][2] = lds32(p + 16);
            fa[buf][mi][3] = lds32(p + 8 * LDS_STRIDE * 4 + 16);
        }
        #pragma unroll
        for (int ni = 0; ni < 8; ni++) {
            uint32_t p = sb + (uint32_t)(ni * 8 * LDS_STRIDE) * 4;
            fb[buf][ni][0] = lds32(p);
            fb[buf][ni][1] = lds32(p + 16);
        }
    };

    // MMA current buffer b while loading next buffer nb from (stg, nks),
    // interleaved at mi granularity (8 loads : 8 MMAs).
    auto step = [&](int b, int nb, uint32_t stg, int nks) {
        const uint32_t sa = stg + aoff + (uint32_t)(nks * 8) * 4;
        const uint32_t sb = stg + (uint32_t)A_FLOATS * 4 + boff + (uint32_t)(nks * 8) * 4;
        #pragma unroll
        for (int mi = 0; mi < 4; mi++) {
            uint32_t p = sa + (uint32_t)(mi * 16 * LDS_STRIDE) * 4;
            fa[nb][mi][0] = lds32(p);
            fa[nb][mi][1] = lds32(p + 8 * LDS_STRIDE * 4);
            fa[nb][mi][2] = lds32(p + 16);
            fa[nb][mi][3] = lds32(p + 8 * LDS_STRIDE * 4 + 16);
            #pragma unroll
            for (int u = 0; u < 2; u++) {
                int ni = 2 * mi + u;
                uint32_t q = sb + (uint32_t)(ni * 8 * LDS_STRIDE) * 4;
                fb[nb][ni][0] = lds32(q);
                fb[nb][ni][1] = lds32(q + 16);
            }
            #pragma unroll
            for (int ni = 0; ni < 8; ni++)
                mma_tf32(acc[mi][ni], fa[b][mi], fb[b][ni]);
        }
    };

    auto mma_all = [&](int b) {
        #pragma unroll
        for (int mi = 0; mi < 4; mi++)
            #pragma unroll
            for (int ni = 0; ni < 8; ni++)
                mma_tf32(acc[mi][ni], fa[b][mi], fb[b][ni]);
    };

    // prologue: 2 stages in flight
    load_stage(0); CP_COMMIT();
    load_stage(1); CP_COMMIT();
    CP_WAIT1();
    __syncthreads();
    load_frags(0, sbase, 0);

    #pragma unroll 1
    for (int kt = 0; kt < KT; kt++) {
        const uint32_t stg = sbase + (uint32_t)(kt % NSTG) * STG_BYTES;

        // ks0: mma buf0, load buf1 <- ks1
        step(0, 1, stg, 1);
        if (kt + 2 < KT) load_stage(kt + 2);
        CP_COMMIT();
        // ks1: mma buf1, load buf0 <- ks2
        step(1, 0, stg, 2);
        // ks2: mma buf0, load buf1 <- ks3
        step(0, 1, stg, 3);
        // ks3: mma buf1, load buf0 <- next tile ks0
        if (kt + 1 < KT) {
            CP_WAIT1();
            __syncthreads();
            step(1, 0, sbase + (uint32_t)((kt + 1) % NSTG) * STG_BYTES, 0);
        } else {
            mma_all(1);
        }
    }

    // epilogue
    #pragma unroll
    for (int mi = 0; mi < 4; mi++) {
        #pragma unroll
        for (int ni = 0; ni < 8; ni++) {
            int r0 = bm + wm + mi * 16 + gid;
            int c0 = bn + wn + ni * 8 + tig * 2;
            #pragma unroll
            for (int h = 0; h < 2; h++) {
                int r = r0 + h * 8;
                size_t off = (size_t)r * N + c0;
                float v0 = acc[mi][ni][2 * h + 0];
                float v1 = acc[mi][ni][2 * h + 1];
                if (FUSE) {
                    v0 = xres[off]     + cs[c0]     * v0;
                    v1 = xres[off + 1] + cs[c0 + 1] * v1;
                }
                float2 st; st.x = v0; st.y = v1;
                *(float2*)(C + off) = st;
            }
        }
    }
}

// ---------------- prep: round weights to tf32 (RNA) ----------------
__global__ void round_We_k(const float* __restrict__ src) {
    size_t i = (size_t)blockIdx.x * blockDim.x + threadIdx.x;
    size_t n4 = (size_t)N1 * KD / 4;
    if (i >= n4) return;
    float4 v = ((const float4*)src)[i];
    v.x = to_tf32(v.x); v.y = to_tf32(v.y); v.z = to_tf32(v.z); v.w = to_tf32(v.w);
    ((float4*)g_We)[i] = v;
}
__global__ void round_Wp_k(const float* __restrict__ src) {
    size_t i = (size_t)blockIdx.x * blockDim.x + threadIdx.x;
    size_t n4 = (size_t)KD * KD / 4;
    if (i >= n4) return;
    float4 v = ((const float4*)src)[i];
    v.x = to_tf32(v.x); v.y = to_tf32(v.y); v.z = to_tf32(v.z); v.w = to_tf32(v.w);
    ((float4*)g_Wp)[i] = v;
}

// ---------------- rmsnorm ----------------
__global__ void __launch_bounds__(256) rmsnorm_k(const float* __restrict__ x) {
    int row = blockIdx.x;
    const float4* xr = (const float4*)(x + (size_t)row * DIMD);
    float4* outr = (float4*)(g_xn + (size_t)row * DIMD);
    int t = threadIdx.x;

    float4 a = xr[t];
    float4 b = xr[t + 256];
    float ss = a.x*a.x + a.y*a.y + a.z*a.z + a.w*a.w
             + b.x*b.x + b.y*b.y + b.z*b.z + b.w*b.w;
    #pragma unroll
    for (int off = 16; off > 0; off >>= 1)
        ss += __shfl_xor_sync(0xffffffffu, ss, off);

    __shared__ float red[8];
    __shared__ float sscale;
    int warp = t >> 5, lane = t & 31;
    if (lane == 0) red[warp] = ss;
    __syncthreads();
    if (t == 0) {
        float tot = 0.f;
        #pragma unroll
        for (int i = 0; i < 8; i++) tot += red[i];
        sscale = rsqrtf(tot * (1.0f / DIMD) + 1.1920928955078125e-07f);
    }
    __syncthreads();
    float sc = sscale;
    a.x = to_tf32(a.x * sc); a.y = to_tf32(a.y * sc); a.z = to_tf32(a.z * sc); a.w = to_tf32(a.w * sc);
    b.x = to_tf32(b.x * sc); b.y = to_tf32(b.y * sc); b.z = to_tf32(b.z * sc); b.w = to_tf32(b.w * sc);
    outr[t] = a;
    outr[t + 256] = b;
}

// ---------------- gate * causal dwconv * gate ----------------
__global__ void __launch_bounds__(256) gateconv_k(const float* __restrict__ cw,
                                                  const float* __restrict__ cb,
                                                  const int* __restrict__ dil_p) {
    int dil = *dil_p;
    size_t idx = (size_t)blockIdx.x * blockDim.x + threadIdx.x;
    if (idx >= (size_t)MTOT * DIMD) return;
    int d = (int)(idx % DIMD);
    int m = (int)(idx / DIMD);
    int s = m % SEQ;

    const float* hr = g_h + (size_t)m * N1;
    float w0 = cw[d * 3 + 0], w1 = cw[d * 3 + 1], w2 = cw[d * 3 + 2];

    float acc = cb[d];
    acc += w2 * (hr[d] * hr[2 * DIMD + d]);
    if (s >= dil) {
        const float* hp = hr - (size_t)dil * N1;
        acc += w1 * (hp[d] * hp[2 * DIMD + d]);
    }
    if (s >= 2 * dil) {
        const float* hp = hr - (size_t)(2 * dil) * N1;
        acc += w0 * (hp[d] * hp[2 * DIMD + d]);
    }
    float Cg = hr[DIMD + d];
    g_o[idx] = to_tf32(Cg * acc);
}

// ---------------- launch ----------------
extern "C" void kernel_launch(void* const* d_in, const int* in_sizes, int n_in,
                              void* d_out, int out_size) {
    const float* x   = (const float*)d_in[0];
    const float* We  = (const float*)d_in[1];
    const float* cw  = (const float*)d_in[2];
    const float* cb  = (const float*)d_in[3];
    const float* Wp  = (const float*)d_in[4];
    const float* cs  = (const float*)d_in[5];
    const int*   dil = (const int*)  d_in[6];
    float* out = (float*)d_out;

    float *p_xn, *p_h, *p_o, *p_We, *p_Wp;
    cudaGetSymbolAddress((void**)&p_xn, g_xn);
    cudaGetSymbolAddress((void**)&p_h,  g_h);
    cudaGetSymbolAddress((void**)&p_o,  g_o);
    cudaGetSymbolAddress((void**)&p_We, g_We);
    cudaGetSymbolAddress((void**)&p_Wp, g_Wp);

    cudaFuncSetAttribute(gemm_k<N1, false>, cudaFuncAttributeMaxDynamicSharedMemorySize, SMEM_SZ);
    cudaFuncSetAttribute(gemm_k<KD, true >, cudaFuncAttributeMaxDynamicSharedMemorySize, SMEM_SZ);

    {
        size_t n4 = (size_t)N1 * KD / 4;
        round_We_k<<<(unsigned)((n4 + 255) / 256), 256>>>(We);
        n4 = (size_t)KD * KD / 4;
        round_Wp_k<<<(unsigned)((n4 + 255) / 256), 256>>>(Wp);
    }

    rmsnorm_k<<<MTOT, 256>>>(x);

    // h = xn @ We^T   [16384 x 6144]
    gemm_k<N1, false><<<dim3(N1 / BN, MTOT / BM), 256, SMEM_SZ>>>(p_xn, p_We, p_h, nullptr, nullptr);

    {
        size_t n = (size_t)MTOT * DIMD;
        gateconv_k<<<(unsigned)((n + 255) / 256), 256>>>(cw, cb, dil);
    }

    // out = x + cs * (o @ Wp^T)   [16384 x 2048]
    gemm_k<KD, true><<<dim3(KD / BN, MTOT / BM), 256, SMEM_SZ>>>(p_o, p_Wp, out, x, cs);
}

// round 9
// speedup vs baseline: 1.3660x; 1.1120x over previous
#include <cuda_runtime.h>
#include <cstdint>
#include <cstddef>

// ---------------- problem constants ----------------
#define DIMD   2048
#define MTOT   16384            // 4*4096 tokens
#define N1     6144             // 3*DIMD
#define KD     2048
#define SEQ    4096

// ---------------- scratch (k-permuted layouts for GEMM operands) ----------
// Within each 8-element k-group, order [0,4,1,5,2,6,3,7]: (k=t, k=t+4) are
// adjacent -> one LDS.64 per fragment pair.
__device__ float g_xn[(size_t)MTOT * KD];
__device__ float g_h [(size_t)MTOT * N1];
__device__ float g_o [(size_t)MTOT * KD];
__device__ float g_We[(size_t)N1  * KD];
__device__ float g_Wp[(size_t)KD  * KD];

// ---------------- helpers ----------------
__device__ __forceinline__ float to_tf32(float x) {
    float r; asm("cvt.rna.tf32.f32 %0, %1;" : "=f"(r) : "f"(x)); return r;
}
__device__ __forceinline__ void cpasync16(void* smem, const void* gmem) {
    uint32_t s = (uint32_t)__cvta_generic_to_shared(smem);
    asm volatile("cp.async.cg.shared.global [%0], [%1], 16;" :: "r"(s), "l"(gmem));
}
#define CP_COMMIT() asm volatile("cp.async.commit_group;")
#define CP_WAIT1()  asm volatile("cp.async.wait_group 1;")

__device__ __forceinline__ uint2 lds64(uint32_t a) {
    uint2 v;
    asm volatile("ld.shared.v2.b32 {%0,%1}, [%2];" : "=r"(v.x), "=r"(v.y) : "r"(a));
    return v;
}

__device__ __forceinline__ void mma_tf32(float c[4], const uint32_t a[4], const uint32_t b[2]) {
    asm volatile(
        "mma.sync.aligned.m16n8k8.row.col.f32.tf32.tf32.f32 "
        "{%0,%1,%2,%3}, {%4,%5,%6,%7}, {%8,%9}, {%0,%1,%2,%3};"
        : "+f"(c[0]), "+f"(c[1]), "+f"(c[2]), "+f"(c[3])
        : "r"(a[0]), "r"(a[1]), "r"(a[2]), "r"(a[3]),
          "r"(b[0]), "r"(b[1]));
}

// interleave 8 consecutive-k floats into permuted order [0,4,1,5,2,6,3,7]
__device__ __forceinline__ void perm_store8(float* dst, float4 a, float4 b) {
    float4 o0, o1;
    o0.x = a.x; o0.y = b.x; o0.z = a.y; o0.w = b.y;
    o1.x = a.z; o1.y = b.z; o1.z = a.w; o1.w = b.w;
    ((float4*)dst)[0] = o0;
    ((float4*)dst)[1] = o1;
}

// ---------------- tf32 GEMM v9: C[M,N] = A[M,K] * B[N,K]^T ----------------
// CTA 128x256, 8 warps (2Mx4N), warp tile 64x64, BK=32, NSTG=3.
// Smem rows are 128B (32 floats), XOR chunk swizzle: phys_chunk = c ^ (row&7)
// -> conflict-free LDS.64 fragment loads (16 per ks instead of 32 LDS.32).
// Register ping-pong + interleaved load/MMA schedule (R8 structure).
constexpr int BM = 128, BN = 256, BK = 32, NSTG = 3;
constexpr int ROW_F = 32;                            // floats per smem row
constexpr int A_FLOATS = BM * ROW_F;                 // 4096
constexpr int B_FLOATS = BN * ROW_F;                 // 8192
constexpr int STG_FLOATS = A_FLOATS + B_FLOATS;      // 12288
constexpr int STG_BYTES  = STG_FLOATS * 4;           // 49152
constexpr int SMEM_SZ = NSTG * STG_BYTES;            // 147456 B

template<int N, bool FUSE>
__global__ void __launch_bounds__(256, 1) gemm_k(const float* __restrict__ A,
                                                 const float* __restrict__ B,
                                                 float* __restrict__ C,
                                                 const float* __restrict__ xres,
                                                 const float* __restrict__ cs) {
    constexpr int K = KD;
    constexpr int KT = K / BK;    // 64
    extern __shared__ float smem[];
    const uint32_t sbase = (uint32_t)__cvta_generic_to_shared(smem);

    const int bm = blockIdx.y * BM;
    const int bn = blockIdx.x * BN;
    const int tid  = threadIdx.x;
    const int warp = tid >> 5, lane = tid & 31;
    const int wm = (warp & 1) * 64;
    const int wn = (warp >> 1) * 64;
    const int gid = lane >> 2, tig = lane & 3;

    float acc[4][8][4];
    #pragma unroll
    for (int mi = 0; mi < 4; mi++)
        #pragma unroll
        for (int ni = 0; ni < 8; ni++)
            #pragma unroll
            for (int r = 0; r < 4; r++) acc[mi][ni][r] = 0.f;

    const float* Abase = A + (size_t)bm * K;
    const float* Bbase = B + (size_t)bn * K;

    auto load_stage = [&](int kt) {
        float* sa = smem + (kt % NSTG) * STG_FLOATS;
        float* sb = sa + A_FLOATS;
        const float* Ag = Abase + kt * BK;
        const float* Bg = Bbase + kt * BK;
        // A: 128 rows x 8 chunks(16B) = 1024, 4 per thread; swizzled dst
        #pragma unroll
        for (int i = 0; i < 4; i++) {
            int c = tid + i * 256;
            int row = c >> 3, ck = c & 7;
            cpasync16(sa + row * ROW_F + ((ck ^ (row & 7)) << 2),
                      Ag + (size_t)row * K + ck * 4);
        }
        // B: 256 rows x 8 chunks = 2048, 8 per thread
        #pragma unroll
        for (int i = 0; i < 8; i++) {
            int c = tid + i * 256;
            int row = c >> 3, ck = c & 7;
            cpasync16(sb + row * ROW_F + ((ck ^ (row & 7)) << 2),
                      Bg + (size_t)row * K + ck * 4);
        }
    };

    uint32_t fa[2][4][4];
    uint32_t fb[2][8][2];

    // per-thread invariants (bytes).  XOR key for all fragment rows is gid.
    const uint32_t arow = (uint32_t)(wm + gid) * 128;
    const uint32_t brow = (uint32_t)(wn + gid) * 128;
    const uint32_t tighi = (uint32_t)(tig >> 1);
    const uint32_t tiglo8 = (uint32_t)(tig & 1) * 8;
    // column byte offset within a row, for ks: ((2*ks + tighi) ^ gid)*16 + tiglo8
    #define COLB(ks) ((((2u * (ks) + tighi) ^ (uint32_t)gid) << 4) + tiglo8)

    // plain fragment load for one buffer
    auto load_frags = [&](int buf, uint32_t stg, int ks) {
        const uint32_t cb = COLB(ks);
        const uint32_t sa = stg + arow + cb;
        const uint32_t sb = stg + (uint32_t)(A_FLOATS * 4) + brow + cb;
        #pragma unroll
        for (int mi = 0; mi < 4; mi++) {
            uint32_t p = sa + (uint32_t)(mi * 16 * 128);
            uint2 v = lds64(p);
            uint2 w = lds64(p + 8 * 128);
            fa[buf][mi][0] = v.x; fa[buf][mi][1] = w.x;
            fa[buf][mi][2] = v.y; fa[buf][mi][3] = w.y;
        }
        #pragma unroll
        for (int ni = 0; ni < 8; ni++) {
            uint2 u = lds64(sb + (uint32_t)(ni * 8 * 128));
            fb[buf][ni][0] = u.x; fb[buf][ni][1] = u.y;
        }
    };

    // MMA buffer b while loading buffer nb from (stg, nks), interleaved at
    // mi granularity (4 LDS.64 : 8 MMAs).
    auto step = [&](int b, int nb, uint32_t stg, int nks) {
        const uint32_t cb = COLB(nks);
        const uint32_t sa = stg + arow + cb;
        const uint32_t sb = stg + (uint32_t)(A_FLOATS * 4) + brow + cb;
        #pragma unroll
        for (int mi = 0; mi < 4; mi++) {
            uint32_t p = sa + (uint32_t)(mi * 16 * 128);
            uint2 v = lds64(p);
            uint2 w = lds64(p + 8 * 128);
            fa[nb][mi][0] = v.x; fa[nb][mi][1] = w.x;
            fa[nb][mi][2] = v.y; fa[nb][mi][3] = w.y;
            #pragma unroll
            for (int u = 0; u < 2; u++) {
                int ni = 2 * mi + u;
                uint2 q = lds64(sb + (uint32_t)(ni * 8 * 128));
                fb[nb][ni][0] = q.x; fb[nb][ni][1] = q.y;
            }
            #pragma unroll
            for (int ni = 0; ni < 8; ni++)
                mma_tf32(acc[mi][ni], fa[b][mi], fb[b][ni]);
        }
    };

    auto mma_all = [&](int b) {
        #pragma unroll
        for (int mi = 0; mi < 4; mi++)
            #pragma unroll
            for (int ni = 0; ni < 8; ni++)
                mma_tf32(acc[mi][ni], fa[b][mi], fb[b][ni]);
    };

    // prologue: 2 stages in flight
    load_stage(0); CP_COMMIT();
    load_stage(1); CP_COMMIT();
    CP_WAIT1();
    __syncthreads();
    load_frags(0, sbase, 0);

    #pragma unroll 1
    for (int kt = 0; kt < KT; kt++) {
        const uint32_t stg = sbase + (uint32_t)(kt % NSTG) * STG_BYTES;

        step(0, 1, stg, 1);
        if (kt + 2 < KT) load_stage(kt + 2);
        CP_COMMIT();
        step(1, 0, stg, 2);
        step(0, 1, stg, 3);
        if (kt + 1 < KT) {
            CP_WAIT1();
            __syncthreads();
            step(1, 0, sbase + (uint32_t)((kt + 1) % NSTG) * STG_BYTES, 0);
        } else {
            mma_all(1);
        }
    }
    #undef COLB

    // epilogue
    #pragma unroll
    for (int mi = 0; mi < 4; mi++) {
        #pragma unroll
        for (int ni = 0; ni < 8; ni++) {
            int r0 = bm + wm + mi * 16 + gid;
            int c0 = bn + wn + ni * 8 + tig * 2;
            #pragma unroll
            for (int h = 0; h < 2; h++) {
                int r = r0 + h * 8;
                size_t off = (size_t)r * N + c0;
                float v0 = acc[mi][ni][2 * h + 0];
                float v1 = acc[mi][ni][2 * h + 1];
                if (FUSE) {
                    v0 = xres[off]     + cs[c0]     * v0;
                    v1 = xres[off + 1] + cs[c0 + 1] * v1;
                }
                float2 st; st.x = v0; st.y = v1;
                *(float2*)(C + off) = st;
            }
        }
    }
}

// ---------------- prep: round weights to tf32 + k-permute ----------------
template<size_t TOTAL>
__global__ void round_perm_k(const float* __restrict__ src, float* __restrict__ dst) {
    size_t i = (size_t)blockIdx.x * blockDim.x + threadIdx.x;   // 8-group index
    if (i >= TOTAL / 8) return;
    float4 a = ((const float4*)src)[2 * i];
    float4 b = ((const float4*)src)[2 * i + 1];
    a.x = to_tf32(a.x); a.y = to_tf32(a.y); a.z = to_tf32(a.z); a.w = to_tf32(a.w);
    b.x = to_tf32(b.x); b.y = to_tf32(b.y); b.z = to_tf32(b.z); b.w = to_tf32(b.w);
    perm_store8(dst + 8 * i, a, b);
}

// ---------------- rmsnorm (emits k-permuted tf32 rows) ----------------
__global__ void __launch_bounds__(256) rmsnorm_k(const float* __restrict__ x) {
    int row = blockIdx.x;
    const float4* xr = (const float4*)(x + (size_t)row * DIMD);
    float* outr = g_xn + (size_t)row * DIMD;
    int t = threadIdx.x;               // thread t owns 8-group t

    float4 a = xr[2 * t];
    float4 b = xr[2 * t + 1];
    float ss = a.x*a.x + a.y*a.y + a.z*a.z + a.w*a.w
             + b.x*b.x + b.y*b.y + b.z*b.z + b.w*b.w;
    #pragma unroll
    for (int off = 16; off > 0; off >>= 1)
        ss += __shfl_xor_sync(0xffffffffu, ss, off);

    __shared__ float red[8];
    __shared__ float sscale;
    int warp = t >> 5, lane = t & 31;
    if (lane == 0) red[warp] = ss;
    __syncthreads();
    if (t == 0) {
        float tot = 0.f;
        #pragma unroll
        for (int i = 0; i < 8; i++) tot += red[i];
        sscale = rsqrtf(tot * (1.0f / DIMD) + 1.1920928955078125e-07f);
    }
    __syncthreads();
    float sc = sscale;
    a.x = to_tf32(a.x * sc); a.y = to_tf32(a.y * sc); a.z = to_tf32(a.z * sc); a.w = to_tf32(a.w * sc);
    b.x = to_tf32(b.x * sc); b.y = to_tf32(b.y * sc); b.z = to_tf32(b.z * sc); b.w = to_tf32(b.w * sc);
    perm_store8(outr + 8 * t, a, b);
}

// ---------------- gate * causal dwconv * gate (emits k-permuted o) -------
__global__ void __launch_bounds__(256) gateconv_k(const float* __restrict__ cw,
                                                  const float* __restrict__ cb,
                                                  const int* __restrict__ dil_p) {
    int dil = *dil_p;
    size_t idx = (size_t)blockIdx.x * blockDim.x + threadIdx.x;
    if (idx >= (size_t)MTOT * (DIMD / 2)) return;
    int r = (int)(idx % (DIMD / 2));
    int m = (int)(idx / (DIMD / 2));
    int s = m % SEQ;
    int gi = r >> 2, j = r & 3;
    int d0 = gi * 8 + j;
    int d1 = d0 + 4;

    const float* hr = g_h + (size_t)m * N1;
    float w00 = cw[d0 * 3 + 0], w01 = cw[d0 * 3 + 1], w02 = cw[d0 * 3 + 2];
    float w10 = cw[d1 * 3 + 0], w11 = cw[d1 * 3 + 1], w12 = cw[d1 * 3 + 2];

    float a0 = cb[d0] + w02 * (hr[d0] * hr[2 * DIMD + d0]);
    float a1 = cb[d1] + w12 * (hr[d1] * hr[2 * DIMD + d1]);
    if (s >= dil) {
        const float* hp = hr - (size_t)dil * N1;
        a0 += w01 * (hp[d0] * hp[2 * DIMD + d0]);
        a1 += w11 * (hp[d1] * hp[2 * DIMD + d1]);
    }
    if (s >= 2 * dil) {
        const float* hp = hr - (size_t)(2 * dil) * N1;
        a0 += w00 * (hp[d0] * hp[2 * DIMD + d0]);
        a1 += w10 * (hp[d1] * hp[2 * DIMD + d1]);
    }
    float2 o;
    o.x = to_tf32(hr[DIMD + d0] * a0);
    o.y = to_tf32(hr[DIMD + d1] * a1);
    *(float2*)(g_o + (size_t)m * DIMD + gi * 8 + 2 * j) = o;
}

// ---------------- launch ----------------
extern "C" void kernel_launch(void* const* d_in, const int* in_sizes, int n_in,
                              void* d_out, int out_size) {
    const float* x   = (const float*)d_in[0];
    const float* We  = (const float*)d_in[1];
    const float* cw  = (const float*)d_in[2];
    const float* cb  = (const float*)d_in[3];
    const float* Wp  = (const float*)d_in[4];
    const float* cs  = (const float*)d_in[5];
    const int*   dil = (const int*)  d_in[6];
    float* out = (float*)d_out;

    float *p_xn, *p_h, *p_o, *p_We, *p_Wp;
    cudaGetSymbolAddress((void**)&p_xn, g_xn);
    cudaGetSymbolAddress((void**)&p_h,  g_h);
    cudaGetSymbolAddress((void**)&p_o,  g_o);
    cudaGetSymbolAddress((void**)&p_We, g_We);
    cudaGetSymbolAddress((void**)&p_Wp, g_Wp);

    cudaFuncSetAttribute(gemm_k<N1, false>, cudaFuncAttributeMaxDynamicSharedMemorySize, SMEM_SZ);
    cudaFuncSetAttribute(gemm_k<KD, true >, cudaFuncAttributeMaxDynamicSharedMemorySize, SMEM_SZ);

    {
        constexpr size_t TWE = (size_t)N1 * KD;
        constexpr size_t TWP = (size_t)KD * KD;
        round_perm_k<TWE><<<(unsigned)((TWE / 8 + 255) / 256), 256>>>(We, p_We);
        round_perm_k<TWP><<<(unsigned)((TWP / 8 + 255) / 256), 256>>>(Wp, p_Wp);
    }

    rmsnorm_k<<<MTOT, 256>>>(x);

    // h = xn @ We^T   [16384 x 6144]
    gemm_k<N1, false><<<dim3(N1 / BN, MTOT / BM), 256, SMEM_SZ>>>(p_xn, p_We, p_h, nullptr, nullptr);

    {
        size_t n = (size_t)MTOT * (DIMD / 2);
        gateconv_k<<<(unsigned)((n + 255) / 256), 256>>>(cw, cb, dil);
    }

    // out = x + cs * (o @ Wp^T)   [16384 x 2048]
    gemm_k<KD, true><<<dim3(KD / BN, MTOT / BM), 256, SMEM_SZ>>>(p_o, p_Wp, out, x, cs);
}